// round 1
// baseline (speedup 1.0000x reference)
#include <cuda_runtime.h>
#include <cuda_bf16.h>

// ---------------- problem constants ----------------
#define BB      2
#define LL      2048
#define DM      2048
#define HH      64
#define PP      64
#define NST     128
#define KK      4
#define CHUNK   256
#define CC      8            // LL / CHUNK
#define DI      4096         // H*P
#define CONV    4352         // DI + 2*NST
#define PROJ    8512         // DI + CONV + HH
#define EPSV    1e-5f

// ---------------- scratch (static device memory; no cudaMalloc allowed) ----
__device__ float g_proj[(size_t)BB * LL * PROJ];        // 139.5 MB
__device__ float g_hbc [(size_t)BB * LL * CONV];        // 71 MB  (conv+silu out)
__device__ float g_dt  [(size_t)BB * LL * HH];
__device__ float g_cum [(size_t)BB * LL * HH];
__device__ float g_s   [(size_t)BB * CC * CHUNK * CHUNK]; // 4 MB (head-indep scores)
__device__ float g_states[(size_t)BB * CC * HH * PP * NST]; // 33.5 MB
__device__ float g_prev  [(size_t)BB * CC * HH * PP * NST]; // 33.5 MB
__device__ float g_y   [(size_t)BB * LL * DI];          // 67 MB (yh, then normed hidden)

// ---------------- generic tiled SGEMM: C = A(MxK) @ B(KxN), row-major ------
// 128x128 tile, BK=8, 256 threads, 8x8 per thread. M%128==0, K%8==0 assumed.
// N guarded (handles N=8512 ragged edge).
__global__ __launch_bounds__(256) void sgemm_kernel(
    const float* __restrict__ A, const float* __restrict__ B,
    float* __restrict__ C, int M, int N, int Kd)
{
    __shared__ float As[8][128];
    __shared__ float Bs[8][128];

    const int tid  = threadIdx.x;
    const int bm   = blockIdx.y, bn = blockIdx.x;
    const int row0 = bm * 128, col0 = bn * 128;

    const int arow = tid >> 1;          // 0..127
    const int acol = (tid & 1) * 4;     // 0 or 4
    const int brow = tid >> 5;          // 0..7
    const int bcol = (tid & 31) * 4;    // 0..124

    const int tr = tid >> 4;            // 0..15
    const int tc = tid & 15;            // 0..15

    float acc[8][8];
#pragma unroll
    for (int i = 0; i < 8; i++)
#pragma unroll
        for (int j = 0; j < 8; j++) acc[i][j] = 0.f;

    const float* Aptr = A + (size_t)(row0 + arow) * Kd + acol;
    const float* Bptr = B + (size_t)brow * N + col0 + bcol;
    const bool bInRange = (col0 + bcol + 3) < N;

    for (int k0 = 0; k0 < Kd; k0 += 8) {
        float4 av = *(const float4*)Aptr;
        As[acol + 0][arow] = av.x;
        As[acol + 1][arow] = av.y;
        As[acol + 2][arow] = av.z;
        As[acol + 3][arow] = av.w;

        float4 bv = make_float4(0.f, 0.f, 0.f, 0.f);
        if (bInRange) bv = *(const float4*)Bptr;
        *(float4*)&Bs[brow][bcol] = bv;

        __syncthreads();

#pragma unroll
        for (int kk = 0; kk < 8; kk++) {
            float4 ra0 = *(const float4*)&As[kk][tr * 8];
            float4 ra1 = *(const float4*)&As[kk][tr * 8 + 4];
            float4 rb0 = *(const float4*)&Bs[kk][tc * 8];
            float4 rb1 = *(const float4*)&Bs[kk][tc * 8 + 4];
            float ra[8] = {ra0.x, ra0.y, ra0.z, ra0.w, ra1.x, ra1.y, ra1.z, ra1.w};
            float rb[8] = {rb0.x, rb0.y, rb0.z, rb0.w, rb1.x, rb1.y, rb1.z, rb1.w};
#pragma unroll
            for (int i = 0; i < 8; i++)
#pragma unroll
                for (int j = 0; j < 8; j++) acc[i][j] += ra[i] * rb[j];
        }
        __syncthreads();
        Aptr += 8;
        Bptr += (size_t)8 * N;
    }

#pragma unroll
    for (int i = 0; i < 8; i++) {
        int r = row0 + tr * 8 + i;
        float* crow = C + (size_t)r * N;
#pragma unroll
        for (int j = 0; j < 8; j++) {
            int cidx = col0 + tc * 8 + j;
            if (cidx < N) crow[cidx] = acc[i][j];
        }
    }
}

// ---------------- depthwise causal conv (K=4) + bias + SiLU ----------------
__global__ void conv_silu_kernel(const float* __restrict__ conv_w,
                                 const float* __restrict__ conv_b)
{
    size_t idx = (size_t)blockIdx.x * blockDim.x + threadIdx.x;
    const size_t total = (size_t)BB * LL * CONV;
    if (idx >= total) return;
    int ch = (int)(idx % CONV);
    size_t bl = idx / CONV;         // b*LL + l
    int l = (int)(bl % LL);

    float acc = conv_b[ch];
#pragma unroll
    for (int k = 0; k < KK; k++) {
        int ls = l - (KK - 1) + k;
        if (ls >= 0)
            acc += g_proj[(bl - (KK - 1) + k) * PROJ + DI + ch] * conv_w[ch * KK + k];
    }
    g_hbc[idx] = acc / (1.f + __expf(-acc));   // silu
}

// ---------------- dt = softplus(raw + bias); cum = chunk-cumsum(dt*A) ------
__global__ void dtcum_kernel(const float* __restrict__ dt_bias,
                             const float* __restrict__ A_log)
{
    int gw   = (blockIdx.x * blockDim.x + threadIdx.x) >> 5;
    int lane = threadIdx.x & 31;
    if (gw >= BB * CC * HH) return;
    int h  = gw % HH;
    int bc = gw / HH;
    int c  = bc % CC;
    int b  = bc / CC;

    float bias = dt_bias[h];
    float Ah   = -__expf(A_log[h]);
    float carry = 0.f;

    for (int t = 0; t < CHUNK / 32; t++) {
        int l = c * CHUNK + t * 32 + lane;
        size_t row = (size_t)b * LL + l;
        float v = g_proj[row * PROJ + DI + CONV + h] + bias;
        float dtv = (v > 20.f) ? v : log1pf(__expf(v));
        g_dt[row * HH + h] = dtv;
        float s = dtv * Ah;
#pragma unroll
        for (int off = 1; off < 32; off <<= 1) {
            float y = __shfl_up_sync(0xffffffffu, s, off);
            if (lane >= off) s += y;
        }
        float cum = carry + s;
        g_cum[row * HH + h] = cum;
        carry = __shfl_sync(0xffffffffu, cum, 31);
    }
}

// ---------------- head-independent scores: s[i,j] = C_i . B_j --------------
__global__ void scores_kernel()
{
    if (blockIdx.y < blockIdx.x) return;   // only lower-triangular tiles used
    int bc = blockIdx.z;
    int b = bc / CC, c = bc % CC;
    int i0 = blockIdx.y * 32, j0 = blockIdx.x * 32;

    __shared__ float Cs[32][129];
    __shared__ float Bsh[32][129];

    int tx = threadIdx.x, ty = threadIdx.y;
    size_t baseRow = (size_t)b * LL + c * CHUNK;

#pragma unroll
    for (int q = 0; q < 4; q++) {
        int n = tx + 32 * q;
        Cs[ty][n]  = g_hbc[(baseRow + i0 + ty) * CONV + DI + NST + n];
        Bsh[ty][n] = g_hbc[(baseRow + j0 + ty) * CONV + DI + n];
    }
    __syncthreads();

    float acc = 0.f;
#pragma unroll
    for (int n = 0; n < NST; n++) acc += Cs[ty][n] * Bsh[tx][n];

    g_s[(size_t)bc * CHUNK * CHUNK + (size_t)(i0 + ty) * CHUNK + j0 + tx] = acc;
}

// ---------------- per-chunk states: st[h,p,n] = sum_l w_l x[l,h,p] B[l,n] --
__global__ __launch_bounds__(256) void states_kernel()
{
    int bch = blockIdx.x;              // (b*CC + c)*HH + h
    int h  = bch % HH;
    int bc = bch / HH;
    int c  = bc % CC, b = bc / CC;

    __shared__ float xs[32][64];
    __shared__ float Bsh[32][129];
    __shared__ float wsh[32];

    int tid = threadIdx.x;
    int p  = tid & 63;
    int n0 = (tid >> 6) * 32;
    size_t baseRow = (size_t)b * LL + c * CHUNK;
    float cumlast = g_cum[(baseRow + CHUNK - 1) * HH + h];

    float acc[32];
#pragma unroll
    for (int k = 0; k < 32; k++) acc[k] = 0.f;

    for (int lt = 0; lt < CHUNK; lt += 32) {
        for (int q = tid; q < 32 * 64; q += 256) {
            int ll = q >> 6, pp = q & 63;
            xs[ll][pp] = g_hbc[(baseRow + lt + ll) * CONV + h * PP + pp];
        }
        for (int q = tid; q < 32 * 128; q += 256) {
            int ll = q >> 7, nn = q & 127;
            Bsh[ll][nn] = g_hbc[(baseRow + lt + ll) * CONV + DI + nn];
        }
        if (tid < 32) {
            size_t r = baseRow + lt + tid;
            wsh[tid] = __expf(cumlast - g_cum[r * HH + h]) * g_dt[r * HH + h];
        }
        __syncthreads();
#pragma unroll 4
        for (int ll = 0; ll < 32; ll++) {
            float xv = wsh[ll] * xs[ll][p];
#pragma unroll
            for (int k = 0; k < 32; k++) acc[k] += xv * Bsh[ll][n0 + k];
        }
        __syncthreads();
    }

    size_t ob = ((size_t)bch * PP + p) * NST + n0;
#pragma unroll
    for (int k = 0; k < 32; k++) g_states[ob + k] = acc[k];
}

// ---------------- inter-chunk scan: prev[c] = sum_{c'<c} decay... ----------
__global__ void scan_kernel()
{
    int idx = blockIdx.x * blockDim.x + threadIdx.x;
    if (idx >= BB * HH * PP * NST) return;
    int n = idx & 127;
    int p = (idx >> 7) & 63;
    int h = (idx >> 13) & 63;
    int b = idx >> 19;

    float prev = 0.f;
#pragma unroll
    for (int c = 0; c < CC; c++) {
        size_t sidx = ((((size_t)(b * CC + c) * HH + h) * PP + p) * NST) + n;
        g_prev[sidx] = prev;
        float cd = __expf(g_cum[((size_t)b * LL + c * CHUNK + CHUNK - 1) * HH + h]);
        prev = cd * prev + g_states[sidx];
    }
}

// ---------------- Y = Y_diag + Y_off + D*x  (one block per (b,c,h)) --------
__global__ __launch_bounds__(256) void ycomb_kernel(const float* __restrict__ D_param)
{
    int bch = blockIdx.x;
    int h  = bch % HH;
    int bc = bch / HH;
    int c  = bc % CC, b = bc / CC;
    int i  = threadIdx.x;       // chunk position owned by this thread

    __shared__ float shcum[CHUNK];
    __shared__ float shdt[CHUNK];
    __shared__ float tile[64][65];     // reused: x-tiles (A) then prev-tiles (B)

    size_t baseRow = (size_t)b * LL + c * CHUNK;
    {
        size_t r = baseRow + i;
        shcum[i] = g_cum[r * HH + h];
        shdt[i]  = g_dt[r * HH + h];
    }
    __syncthreads();

    float cum_i = shcum[i];
    float acc[64];
#pragma unroll
    for (int p = 0; p < 64; p++) acc[p] = 0.f;

    const float* srow = &g_s[(size_t)bc * CHUNK * CHUNK + (size_t)i * CHUNK];

    // phase A: intra-chunk (diag) term
    for (int jt = 0; jt < CHUNK; jt += 64) {
        for (int q = threadIdx.x; q < 64 * 64; q += 256) {
            int jj = q >> 6, pp = q & 63;
            tile[jj][pp] = g_hbc[(baseRow + jt + jj) * CONV + h * PP + pp];
        }
        __syncthreads();
        for (int jj = 0; jj < 64; jj++) {
            int j = jt + jj;
            if (j > i) break;
            float w = srow[j] * __expf(cum_i - shcum[j]) * shdt[j];
#pragma unroll
            for (int p = 0; p < 64; p++) acc[p] += w * tile[jj][p];
        }
        __syncthreads();
    }

    // phase B: inter-chunk (off) term via prev_states
    float e_i = __expf(cum_i);
    size_t prevBase = (size_t)bch * PP * NST;
    for (int nt = 0; nt < NST; nt += 64) {
        for (int q = threadIdx.x; q < 64 * 64; q += 256) {
            int pp = q >> 6, nn = q & 63;
            tile[nn][pp] = g_prev[prevBase + (size_t)pp * NST + nt + nn];
        }
        __syncthreads();
        const float* Crow = &g_hbc[(baseRow + i) * CONV + DI + NST + nt];
        for (int nn = 0; nn < 64; nn++) {
            float wv = e_i * Crow[nn];
#pragma unroll
            for (int p = 0; p < 64; p++) acc[p] += wv * tile[nn][p];
        }
        __syncthreads();
    }

    // phase C: + D*x, write out
    float Dh = D_param[h];
    const float* xrow = &g_hbc[(baseRow + i) * CONV + h * PP];
    float* yrow = &g_y[(baseRow + i) * DI + h * PP];
#pragma unroll
    for (int p = 0; p < 64; p++) yrow[p] = acc[p] + Dh * xrow[p];
}

// ---------------- gated RMSNorm (in-place on g_y) ---------------------------
__global__ __launch_bounds__(256) void gatenorm_kernel(const float* __restrict__ norm_w)
{
    int row = blockIdx.x;   // 0 .. BB*LL-1
    __shared__ float sh[DI];
    __shared__ float red[256];

    const float* yrow = &g_y[(size_t)row * DI];
    const float* grow = &g_proj[(size_t)row * PROJ];

    float local = 0.f;
    for (int d = threadIdx.x; d < DI; d += 256) {
        float g  = grow[d];
        float hv = yrow[d] * (g / (1.f + __expf(-g)));
        sh[d] = hv;
        local += hv * hv;
    }
    red[threadIdx.x] = local;
    __syncthreads();
    for (int s = 128; s > 0; s >>= 1) {
        if (threadIdx.x < s) red[threadIdx.x] += red[threadIdx.x + s];
        __syncthreads();
    }
    float rms = rsqrtf(red[0] / (float)DI + EPSV);

    float* orow = &g_y[(size_t)row * DI];
    for (int d = threadIdx.x; d < DI; d += 256)
        orow[d] = sh[d] * rms * norm_w[d];
}

// ---------------- launcher ---------------------------------------------------
extern "C" void kernel_launch(void* const* d_in, const int* in_sizes, int n_in,
                              void* d_out, int out_size)
{
    const float* hs       = (const float*)d_in[0];
    const float* in_proj  = (const float*)d_in[1];
    const float* conv_w   = (const float*)d_in[2];
    const float* conv_b   = (const float*)d_in[3];
    const float* dt_bias  = (const float*)d_in[4];
    const float* A_log    = (const float*)d_in[5];
    const float* D_param  = (const float*)d_in[6];
    const float* norm_w   = (const float*)d_in[7];
    const float* out_proj = (const float*)d_in[8];
    float* out = (float*)d_out;

    float* proj_ptr;   cudaGetSymbolAddress((void**)&proj_ptr, g_proj);
    float* y_ptr;      cudaGetSymbolAddress((void**)&y_ptr, g_y);

    const int M = BB * LL;   // 4096

    // 1) in-projection GEMM: (4096 x 2048) @ (2048 x 8512)
    {
        dim3 grid((PROJ + 127) / 128, M / 128);
        sgemm_kernel<<<grid, 256>>>(hs, in_proj, proj_ptr, M, PROJ, DM);
    }
    // 2) depthwise conv + silu
    {
        size_t total = (size_t)BB * LL * CONV;
        conv_silu_kernel<<<(unsigned)((total + 255) / 256), 256>>>(conv_w, conv_b);
    }
    // 3) dt softplus + chunk cumsum
    dtcum_kernel<<<(BB * CC * HH * 32 + 255) / 256, 256>>>(dt_bias, A_log);
    // 4) head-independent CB scores
    {
        dim3 grid(CHUNK / 32, CHUNK / 32, BB * CC);
        scores_kernel<<<grid, dim3(32, 32)>>>();
    }
    // 5) per-chunk states
    states_kernel<<<BB * CC * HH, 256>>>();
    // 6) inter-chunk scan
    scan_kernel<<<(BB * HH * PP * NST + 255) / 256, 256>>>();
    // 7) Y = diag + off + D*x
    ycomb_kernel<<<BB * CC * HH, 256>>>(D_param);
    // 8) gated RMSNorm
    gatenorm_kernel<<<BB * LL, 256>>>(norm_w);
    // 9) out-projection GEMM: (4096 x 4096) @ (4096 x 2048) -> d_out
    {
        dim3 grid(DM / 128, M / 128);
        sgemm_kernel<<<grid, 256>>>(y_ptr, out_proj, out, M, DM, DI);
    }
    (void)in_sizes; (void)n_in; (void)out_size;
}

// round 2
// speedup vs baseline: 2.4186x; 2.4186x over previous
#include <cuda_runtime.h>
#include <cuda_bf16.h>

// ---------------- problem constants ----------------
#define BB      2
#define LL      2048
#define DM      2048
#define HH      64
#define PP      64
#define NST     128
#define KK      4
#define CHUNK   256
#define CC      8            // LL / CHUNK
#define DI      4096         // H*P
#define CONV    4352         // DI + 2*NST
#define PROJ    8512         // DI + CONV + HH
#define EPSV    1e-5f

// ---------------- scratch (static device memory; no cudaMalloc allowed) ----
__device__ float g_proj[(size_t)BB * LL * PROJ];        // 139.5 MB
__device__ float g_hbc [(size_t)BB * LL * CONV];        // 71 MB  (conv+silu out)
__device__ float g_dt  [(size_t)BB * LL * HH];
__device__ float g_cum [(size_t)BB * LL * HH];
__device__ float g_s   [(size_t)BB * CC * CHUNK * CHUNK]; // 4 MB (head-indep scores)
__device__ float g_states[(size_t)BB * CC * HH * PP * NST]; // 33.5 MB
__device__ float g_prev  [(size_t)BB * CC * HH * PP * NST]; // 33.5 MB
__device__ float g_y   [(size_t)BB * LL * DI];          // 67 MB (yh, then normed hidden)

// ---------------- tf32 helpers ----------------------------------------------
__device__ __forceinline__ unsigned f2tf32(float f) {
    unsigned r;
    asm("cvt.rna.tf32.f32 %0, %1;" : "=r"(r) : "f"(f));
    return r;
}

// ---------------- TF32 tensor-core GEMM: C = A(MxK) @ B(KxN), row-major -----
// 128x128 block tile, 4 warps (2x2), each warp 64x64 via m16n8k8 mma.
// K-step = 16. M%128==0, K%16==0 assumed; N ragged-guarded.
__global__ __launch_bounds__(128) void tf32_gemm_kernel(
    const float* __restrict__ A, const float* __restrict__ B,
    float* __restrict__ C, int M, int N, int Kd)
{
    __shared__ unsigned As[128][20];   // m-major, stride 20 -> conflict-free frags
    __shared__ unsigned Bs[16][136];   // k-major, stride 136 -> conflict-free frags

    const int tid  = threadIdx.x;
    const int lane = tid & 31;
    const int warp = tid >> 5;
    const int wm = (warp >> 1) * 64;   // warp row offset in tile
    const int wn = (warp & 1) * 64;    // warp col offset in tile
    const int row0 = blockIdx.y * 128, col0 = blockIdx.x * 128;

    const int g  = lane >> 2;          // 0..7
    const int t4 = lane & 3;           // 0..3

    // global-load mapping
    const int ar = tid >> 2;           // A row within tile (plus q*32)
    const int ac = (tid & 3) * 4;      // A k-col (float4)
    const int br = tid >> 5;           // B k-row within tile (plus q*4)
    const int bc = lane * 4;           // B col (float4)
    const bool bOk = (col0 + bc + 3) < N;

    float acc[4][8][4];
#pragma unroll
    for (int m = 0; m < 4; m++)
#pragma unroll
        for (int n = 0; n < 8; n++)
#pragma unroll
            for (int q = 0; q < 4; q++) acc[m][n][q] = 0.f;

    float4 ra[4], rb[4];

    // prologue: load first k-block into registers
#pragma unroll
    for (int q = 0; q < 4; q++) {
        ra[q] = *(const float4*)&A[(size_t)(row0 + ar + q * 32) * Kd + ac];
        rb[q] = bOk ? *(const float4*)&B[(size_t)(br + q * 4) * N + col0 + bc]
                    : make_float4(0.f, 0.f, 0.f, 0.f);
    }

    for (int k0 = 0; k0 < Kd; k0 += 16) {
        // commit registers -> smem (converted to tf32)
#pragma unroll
        for (int q = 0; q < 4; q++) {
            uint4 av = make_uint4(f2tf32(ra[q].x), f2tf32(ra[q].y),
                                  f2tf32(ra[q].z), f2tf32(ra[q].w));
            *(uint4*)&As[ar + q * 32][ac] = av;
            uint4 bv = make_uint4(f2tf32(rb[q].x), f2tf32(rb[q].y),
                                  f2tf32(rb[q].z), f2tf32(rb[q].w));
            *(uint4*)&Bs[br + q * 4][bc] = bv;
        }
        __syncthreads();

        // prefetch next k-block
        if (k0 + 16 < Kd) {
            int kn = k0 + 16;
#pragma unroll
            for (int q = 0; q < 4; q++) {
                ra[q] = *(const float4*)&A[(size_t)(row0 + ar + q * 32) * Kd + kn + ac];
                rb[q] = bOk ? *(const float4*)&B[(size_t)(kn + br + q * 4) * N + col0 + bc]
                            : make_float4(0.f, 0.f, 0.f, 0.f);
            }
        }

        // two k=8 sub-steps of mma
#pragma unroll
        for (int ks = 0; ks < 16; ks += 8) {
            unsigned af[4][4], bf[8][2];
#pragma unroll
            for (int mt = 0; mt < 4; mt++) {
                int r = wm + mt * 16;
                af[mt][0] = As[r + g][ks + t4];
                af[mt][1] = As[r + g + 8][ks + t4];
                af[mt][2] = As[r + g][ks + t4 + 4];
                af[mt][3] = As[r + g + 8][ks + t4 + 4];
            }
#pragma unroll
            for (int nt = 0; nt < 8; nt++) {
                int cB = wn + nt * 8 + g;
                bf[nt][0] = Bs[ks + t4][cB];
                bf[nt][1] = Bs[ks + t4 + 4][cB];
            }
#pragma unroll
            for (int mt = 0; mt < 4; mt++)
#pragma unroll
                for (int nt = 0; nt < 8; nt++) {
                    asm volatile(
                        "mma.sync.aligned.m16n8k8.row.col.f32.tf32.tf32.f32 "
                        "{%0,%1,%2,%3}, {%4,%5,%6,%7}, {%8,%9}, {%0,%1,%2,%3};"
                        : "+f"(acc[mt][nt][0]), "+f"(acc[mt][nt][1]),
                          "+f"(acc[mt][nt][2]), "+f"(acc[mt][nt][3])
                        : "r"(af[mt][0]), "r"(af[mt][1]),
                          "r"(af[mt][2]), "r"(af[mt][3]),
                          "r"(bf[nt][0]), "r"(bf[nt][1]));
                }
        }
        __syncthreads();
    }

    // epilogue: c0/c1 at (row, col), (row, col+1); c2/c3 at (row+8, ...)
#pragma unroll
    for (int mt = 0; mt < 4; mt++) {
        int r = row0 + wm + mt * 16 + g;
#pragma unroll
        for (int nt = 0; nt < 8; nt++) {
            int cidx = col0 + wn + nt * 8 + t4 * 2;
            if (cidx < N) {
                *(float2*)&C[(size_t)r * N + cidx] =
                    make_float2(acc[mt][nt][0], acc[mt][nt][1]);
                *(float2*)&C[(size_t)(r + 8) * N + cidx] =
                    make_float2(acc[mt][nt][2], acc[mt][nt][3]);
            }
        }
    }
}

// ---------------- depthwise causal conv (K=4) + bias + SiLU ----------------
__global__ void conv_silu_kernel(const float* __restrict__ conv_w,
                                 const float* __restrict__ conv_b)
{
    size_t idx = (size_t)blockIdx.x * blockDim.x + threadIdx.x;
    const size_t total = (size_t)BB * LL * CONV;
    if (idx >= total) return;
    int ch = (int)(idx % CONV);
    size_t bl = idx / CONV;         // b*LL + l
    int l = (int)(bl % LL);

    float acc = conv_b[ch];
#pragma unroll
    for (int k = 0; k < KK; k++) {
        int ls = l - (KK - 1) + k;
        if (ls >= 0)
            acc += g_proj[(bl - (KK - 1) + k) * PROJ + DI + ch] * conv_w[ch * KK + k];
    }
    g_hbc[idx] = acc / (1.f + __expf(-acc));   // silu
}

// ---------------- dt = softplus(raw + bias); cum = chunk-cumsum(dt*A) ------
__global__ void dtcum_kernel(const float* __restrict__ dt_bias,
                             const float* __restrict__ A_log)
{
    int gw   = (blockIdx.x * blockDim.x + threadIdx.x) >> 5;
    int lane = threadIdx.x & 31;
    if (gw >= BB * CC * HH) return;
    int h  = gw % HH;
    int bc = gw / HH;
    int c  = bc % CC;
    int b  = bc / CC;

    float bias = dt_bias[h];
    float Ah   = -__expf(A_log[h]);
    float carry = 0.f;

    for (int t = 0; t < CHUNK / 32; t++) {
        int l = c * CHUNK + t * 32 + lane;
        size_t row = (size_t)b * LL + l;
        float v = g_proj[row * PROJ + DI + CONV + h] + bias;
        float dtv = (v > 20.f) ? v : log1pf(__expf(v));
        g_dt[row * HH + h] = dtv;
        float s = dtv * Ah;
#pragma unroll
        for (int off = 1; off < 32; off <<= 1) {
            float y = __shfl_up_sync(0xffffffffu, s, off);
            if (lane >= off) s += y;
        }
        float cum = carry + s;
        g_cum[row * HH + h] = cum;
        carry = __shfl_sync(0xffffffffu, cum, 31);
    }
}

// ---------------- head-independent scores: s[i,j] = C_i . B_j --------------
__global__ void scores_kernel()
{
    if (blockIdx.y < blockIdx.x) return;   // only lower-triangular tiles used
    int bc = blockIdx.z;
    int b = bc / CC, c = bc % CC;
    int i0 = blockIdx.y * 32, j0 = blockIdx.x * 32;

    __shared__ float Cs[32][129];
    __shared__ float Bsh[32][129];

    int tx = threadIdx.x, ty = threadIdx.y;
    size_t baseRow = (size_t)b * LL + c * CHUNK;

#pragma unroll
    for (int q = 0; q < 4; q++) {
        int n = tx + 32 * q;
        Cs[ty][n]  = g_hbc[(baseRow + i0 + ty) * CONV + DI + NST + n];
        Bsh[ty][n] = g_hbc[(baseRow + j0 + ty) * CONV + DI + n];
    }
    __syncthreads();

    float acc = 0.f;
#pragma unroll
    for (int n = 0; n < NST; n++) acc += Cs[ty][n] * Bsh[tx][n];

    g_s[(size_t)bc * CHUNK * CHUNK + (size_t)(i0 + ty) * CHUNK + j0 + tx] = acc;
}

// ---------------- per-chunk states: st[h,p,n] = sum_l w_l x[l,h,p] B[l,n] --
__global__ __launch_bounds__(256) void states_kernel()
{
    int bch = blockIdx.x;              // (b*CC + c)*HH + h
    int h  = bch % HH;
    int bc = bch / HH;
    int c  = bc % CC, b = bc / CC;

    __shared__ float xs[32][64];
    __shared__ float Bsh[32][129];
    __shared__ float wsh[32];

    int tid = threadIdx.x;
    int p  = tid & 63;
    int n0 = (tid >> 6) * 32;
    size_t baseRow = (size_t)b * LL + c * CHUNK;
    float cumlast = g_cum[(baseRow + CHUNK - 1) * HH + h];

    float acc[32];
#pragma unroll
    for (int k = 0; k < 32; k++) acc[k] = 0.f;

    for (int lt = 0; lt < CHUNK; lt += 32) {
        for (int q = tid; q < 32 * 64; q += 256) {
            int ll = q >> 6, pp = q & 63;
            xs[ll][pp] = g_hbc[(baseRow + lt + ll) * CONV + h * PP + pp];
        }
        for (int q = tid; q < 32 * 128; q += 256) {
            int ll = q >> 7, nn = q & 127;
            Bsh[ll][nn] = g_hbc[(baseRow + lt + ll) * CONV + DI + nn];
        }
        if (tid < 32) {
            size_t r = baseRow + lt + tid;
            wsh[tid] = __expf(cumlast - g_cum[r * HH + h]) * g_dt[r * HH + h];
        }
        __syncthreads();
#pragma unroll 4
        for (int ll = 0; ll < 32; ll++) {
            float xv = wsh[ll] * xs[ll][p];
#pragma unroll
            for (int k = 0; k < 32; k++) acc[k] += xv * Bsh[ll][n0 + k];
        }
        __syncthreads();
    }

    size_t ob = ((size_t)bch * PP + p) * NST + n0;
#pragma unroll
    for (int k = 0; k < 32; k++) g_states[ob + k] = acc[k];
}

// ---------------- inter-chunk scan: prev[c] = sum_{c'<c} decay... ----------
__global__ void scan_kernel()
{
    int idx = blockIdx.x * blockDim.x + threadIdx.x;
    if (idx >= BB * HH * PP * NST) return;
    int n = idx & 127;
    int p = (idx >> 7) & 63;
    int h = (idx >> 13) & 63;
    int b = idx >> 19;

    float prev = 0.f;
#pragma unroll
    for (int c = 0; c < CC; c++) {
        size_t sidx = ((((size_t)(b * CC + c) * HH + h) * PP + p) * NST) + n;
        g_prev[sidx] = prev;
        float cd = __expf(g_cum[((size_t)b * LL + c * CHUNK + CHUNK - 1) * HH + h]);
        prev = cd * prev + g_states[sidx];
    }
}

// ---------------- Y = Y_diag + Y_off + D*x  (one block per (b,c,h)) --------
__global__ __launch_bounds__(256) void ycomb_kernel(const float* __restrict__ D_param)
{
    int bch = blockIdx.x;
    int h  = bch % HH;
    int bc = bch / HH;
    int c  = bc % CC, b = bc / CC;
    int i  = threadIdx.x;       // chunk position owned by this thread

    __shared__ float shcum[CHUNK];
    __shared__ float shdt[CHUNK];
    __shared__ float tile[64][65];     // reused: x-tiles (A) then prev-tiles (B)

    size_t baseRow = (size_t)b * LL + c * CHUNK;
    {
        size_t r = baseRow + i;
        shcum[i] = g_cum[r * HH + h];
        shdt[i]  = g_dt[r * HH + h];
    }
    __syncthreads();

    float cum_i = shcum[i];
    float acc[64];
#pragma unroll
    for (int p = 0; p < 64; p++) acc[p] = 0.f;

    const float* srow = &g_s[(size_t)bc * CHUNK * CHUNK + (size_t)i * CHUNK];

    // phase A: intra-chunk (diag) term
    for (int jt = 0; jt < CHUNK; jt += 64) {
        for (int q = threadIdx.x; q < 64 * 64; q += 256) {
            int jj = q >> 6, pp = q & 63;
            tile[jj][pp] = g_hbc[(baseRow + jt + jj) * CONV + h * PP + pp];
        }
        __syncthreads();
        for (int jj = 0; jj < 64; jj++) {
            int j = jt + jj;
            if (j > i) break;
            float w = srow[j] * __expf(cum_i - shcum[j]) * shdt[j];
#pragma unroll
            for (int p = 0; p < 64; p++) acc[p] += w * tile[jj][p];
        }
        __syncthreads();
    }

    // phase B: inter-chunk (off) term via prev_states
    float e_i = __expf(cum_i);
    size_t prevBase = (size_t)bch * PP * NST;
    for (int nt = 0; nt < NST; nt += 64) {
        for (int q = threadIdx.x; q < 64 * 64; q += 256) {
            int pp = q >> 6, nn = q & 63;
            tile[nn][pp] = g_prev[prevBase + (size_t)pp * NST + nt + nn];
        }
        __syncthreads();
        const float* Crow = &g_hbc[(baseRow + i) * CONV + DI + NST + nt];
        for (int nn = 0; nn < 64; nn++) {
            float wv = e_i * Crow[nn];
#pragma unroll
            for (int p = 0; p < 64; p++) acc[p] += wv * tile[nn][p];
        }
        __syncthreads();
    }

    // phase C: + D*x, write out
    float Dh = D_param[h];
    const float* xrow = &g_hbc[(baseRow + i) * CONV + h * PP];
    float* yrow = &g_y[(baseRow + i) * DI + h * PP];
#pragma unroll
    for (int p = 0; p < 64; p++) yrow[p] = acc[p] + Dh * xrow[p];
}

// ---------------- gated RMSNorm (in-place on g_y) ---------------------------
__global__ __launch_bounds__(256) void gatenorm_kernel(const float* __restrict__ norm_w)
{
    int row = blockIdx.x;   // 0 .. BB*LL-1
    __shared__ float sh[DI];
    __shared__ float red[256];

    const float* yrow = &g_y[(size_t)row * DI];
    const float* grow = &g_proj[(size_t)row * PROJ];

    float local = 0.f;
    for (int d = threadIdx.x; d < DI; d += 256) {
        float g  = grow[d];
        float hv = yrow[d] * (g / (1.f + __expf(-g)));
        sh[d] = hv;
        local += hv * hv;
    }
    red[threadIdx.x] = local;
    __syncthreads();
    for (int s = 128; s > 0; s >>= 1) {
        if (threadIdx.x < s) red[threadIdx.x] += red[threadIdx.x + s];
        __syncthreads();
    }
    float rms = rsqrtf(red[0] / (float)DI + EPSV);

    float* orow = &g_y[(size_t)row * DI];
    for (int d = threadIdx.x; d < DI; d += 256)
        orow[d] = sh[d] * rms * norm_w[d];
}

// ---------------- launcher ---------------------------------------------------
extern "C" void kernel_launch(void* const* d_in, const int* in_sizes, int n_in,
                              void* d_out, int out_size)
{
    const float* hs       = (const float*)d_in[0];
    const float* in_proj  = (const float*)d_in[1];
    const float* conv_w   = (const float*)d_in[2];
    const float* conv_b   = (const float*)d_in[3];
    const float* dt_bias  = (const float*)d_in[4];
    const float* A_log    = (const float*)d_in[5];
    const float* D_param  = (const float*)d_in[6];
    const float* norm_w   = (const float*)d_in[7];
    const float* out_proj = (const float*)d_in[8];
    float* out = (float*)d_out;

    float* proj_ptr;   cudaGetSymbolAddress((void**)&proj_ptr, g_proj);
    float* y_ptr;      cudaGetSymbolAddress((void**)&y_ptr, g_y);

    const int M = BB * LL;   // 4096

    // 1) in-projection GEMM: (4096 x 2048) @ (2048 x 8512)  [tf32 tensor cores]
    {
        dim3 grid((PROJ + 127) / 128, M / 128);
        tf32_gemm_kernel<<<grid, 128>>>(hs, in_proj, proj_ptr, M, PROJ, DM);
    }
    // 2) depthwise conv + silu
    {
        size_t total = (size_t)BB * LL * CONV;
        conv_silu_kernel<<<(unsigned)((total + 255) / 256), 256>>>(conv_w, conv_b);
    }
    // 3) dt softplus + chunk cumsum
    dtcum_kernel<<<(BB * CC * HH * 32 + 255) / 256, 256>>>(dt_bias, A_log);
    // 4) head-independent CB scores
    {
        dim3 grid(CHUNK / 32, CHUNK / 32, BB * CC);
        scores_kernel<<<grid, dim3(32, 32)>>>();
    }
    // 5) per-chunk states
    states_kernel<<<BB * CC * HH, 256>>>();
    // 6) inter-chunk scan
    scan_kernel<<<(BB * HH * PP * NST + 255) / 256, 256>>>();
    // 7) Y = diag + off + D*x
    ycomb_kernel<<<BB * CC * HH, 256>>>(D_param);
    // 8) gated RMSNorm
    gatenorm_kernel<<<BB * LL, 256>>>(norm_w);
    // 9) out-projection GEMM: (4096 x 4096) @ (4096 x 2048) -> d_out [tf32]
    {
        dim3 grid(DM / 128, M / 128);
        tf32_gemm_kernel<<<grid, 128>>>(y_ptr, out_proj, out, M, DM, DI);
    }
    (void)in_sizes; (void)n_in; (void)out_size;
}

// round 3
// speedup vs baseline: 2.5960x; 1.0734x over previous
#include <cuda_runtime.h>
#include <cuda_bf16.h>

// ---------------- problem constants ----------------
#define BB      2
#define LL      2048
#define DM      2048
#define HH      64
#define PP      64
#define NST     128
#define KK      4
#define CHUNK   256
#define CC      8            // LL / CHUNK
#define DI      4096         // H*P
#define CONV    4352         // DI + 2*NST
#define PROJ    8512         // DI + CONV + HH
#define EPSV    1e-5f

// ---------------- scratch (static device memory) ---------------------------
__device__ float g_proj[(size_t)BB * LL * PROJ];
__device__ float g_hbc [(size_t)BB * LL * CONV];
__device__ float g_dt  [(size_t)BB * LL * HH];
__device__ float g_cum [(size_t)BB * LL * HH];
__device__ float g_s   [(size_t)BB * CC * CHUNK * CHUNK];
__device__ float g_states[(size_t)BB * CC * HH * PP * NST];
__device__ float g_prev  [(size_t)BB * CC * HH * PP * NST];
__device__ float g_y   [(size_t)BB * LL * DI];

// ---------------- tf32 helpers ----------------------------------------------
__device__ __forceinline__ unsigned f2tf32(float f) {
    unsigned r;
    asm("cvt.rna.tf32.f32 %0, %1;" : "=r"(r) : "f"(f));
    return r;
}

// ---------------- TF32 GEMM v2: 256 thr, 128x128x16, double-buffered --------
__global__ __launch_bounds__(256) void tf32_gemm_kernel(
    const float* __restrict__ A, const float* __restrict__ B,
    float* __restrict__ C, int M, int N, int Kd)
{
    __shared__ unsigned As[2][128][20];   // [m][k], stride 20
    __shared__ unsigned Bs[2][16][136];   // [k][n], stride 136

    const int tid  = threadIdx.x;
    const int lane = tid & 31;
    const int warp = tid >> 5;
    const int wm = (warp >> 2) * 64;      // warp M offset (0/64)
    const int wn = (warp & 3) * 32;       // warp N offset (0/32/64/96)
    const int row0 = blockIdx.y * 128, col0 = blockIdx.x * 128;

    const int g  = lane >> 2;             // 0..7
    const int t4 = lane & 3;              // 0..3

    const int ar = tid >> 2;              // 0..63 (+64)
    const int ac = (tid & 3) * 4;
    const int br = tid >> 5;              // 0..7 (+8)
    const int bc = (tid & 31) * 4;
    const bool bOk = (col0 + bc + 3) < N;

    float acc[4][4][4];
#pragma unroll
    for (int m = 0; m < 4; m++)
#pragma unroll
        for (int n = 0; n < 4; n++)
#pragma unroll
            for (int q = 0; q < 4; q++) acc[m][n][q] = 0.f;

    float4 ra[2], rb[2];
    // prologue: k-block 0
    ra[0] = *(const float4*)&A[(size_t)(row0 + ar) * Kd + ac];
    ra[1] = *(const float4*)&A[(size_t)(row0 + ar + 64) * Kd + ac];
    rb[0] = bOk ? *(const float4*)&B[(size_t)br * N + col0 + bc] : make_float4(0,0,0,0);
    rb[1] = bOk ? *(const float4*)&B[(size_t)(br + 8) * N + col0 + bc] : make_float4(0,0,0,0);
    {
        *(uint4*)&As[0][ar][ac]      = make_uint4(f2tf32(ra[0].x), f2tf32(ra[0].y), f2tf32(ra[0].z), f2tf32(ra[0].w));
        *(uint4*)&As[0][ar + 64][ac] = make_uint4(f2tf32(ra[1].x), f2tf32(ra[1].y), f2tf32(ra[1].z), f2tf32(ra[1].w));
        *(uint4*)&Bs[0][br][bc]      = make_uint4(f2tf32(rb[0].x), f2tf32(rb[0].y), f2tf32(rb[0].z), f2tf32(rb[0].w));
        *(uint4*)&Bs[0][br + 8][bc]  = make_uint4(f2tf32(rb[1].x), f2tf32(rb[1].y), f2tf32(rb[1].z), f2tf32(rb[1].w));
    }
    __syncthreads();

    int buf = 0;
    for (int k0 = 0; k0 < Kd; k0 += 16) {
        const bool more = (k0 + 16) < Kd;
        if (more) {
            int kn = k0 + 16;
            ra[0] = *(const float4*)&A[(size_t)(row0 + ar) * Kd + kn + ac];
            ra[1] = *(const float4*)&A[(size_t)(row0 + ar + 64) * Kd + kn + ac];
            rb[0] = bOk ? *(const float4*)&B[(size_t)(kn + br) * N + col0 + bc] : make_float4(0,0,0,0);
            rb[1] = bOk ? *(const float4*)&B[(size_t)(kn + br + 8) * N + col0 + bc] : make_float4(0,0,0,0);
        }

#pragma unroll
        for (int ks = 0; ks < 16; ks += 8) {
            unsigned af[4][4], bf[4][2];
#pragma unroll
            for (int mt = 0; mt < 4; mt++) {
                int r = wm + mt * 16;
                af[mt][0] = As[buf][r + g][ks + t4];
                af[mt][1] = As[buf][r + g + 8][ks + t4];
                af[mt][2] = As[buf][r + g][ks + t4 + 4];
                af[mt][3] = As[buf][r + g + 8][ks + t4 + 4];
            }
#pragma unroll
            for (int nt = 0; nt < 4; nt++) {
                int cB = wn + nt * 8 + g;
                bf[nt][0] = Bs[buf][ks + t4][cB];
                bf[nt][1] = Bs[buf][ks + t4 + 4][cB];
            }
#pragma unroll
            for (int mt = 0; mt < 4; mt++)
#pragma unroll
                for (int nt = 0; nt < 4; nt++) {
                    asm volatile(
                        "mma.sync.aligned.m16n8k8.row.col.f32.tf32.tf32.f32 "
                        "{%0,%1,%2,%3}, {%4,%5,%6,%7}, {%8,%9}, {%0,%1,%2,%3};"
                        : "+f"(acc[mt][nt][0]), "+f"(acc[mt][nt][1]),
                          "+f"(acc[mt][nt][2]), "+f"(acc[mt][nt][3])
                        : "r"(af[mt][0]), "r"(af[mt][1]),
                          "r"(af[mt][2]), "r"(af[mt][3]),
                          "r"(bf[nt][0]), "r"(bf[nt][1]));
                }
        }

        if (more) {
            int nb = buf ^ 1;
            *(uint4*)&As[nb][ar][ac]      = make_uint4(f2tf32(ra[0].x), f2tf32(ra[0].y), f2tf32(ra[0].z), f2tf32(ra[0].w));
            *(uint4*)&As[nb][ar + 64][ac] = make_uint4(f2tf32(ra[1].x), f2tf32(ra[1].y), f2tf32(ra[1].z), f2tf32(ra[1].w));
            *(uint4*)&Bs[nb][br][bc]      = make_uint4(f2tf32(rb[0].x), f2tf32(rb[0].y), f2tf32(rb[0].z), f2tf32(rb[0].w));
            *(uint4*)&Bs[nb][br + 8][bc]  = make_uint4(f2tf32(rb[1].x), f2tf32(rb[1].y), f2tf32(rb[1].z), f2tf32(rb[1].w));
            __syncthreads();
            buf = nb;
        }
    }

#pragma unroll
    for (int mt = 0; mt < 4; mt++) {
        int r = row0 + wm + mt * 16 + g;
#pragma unroll
        for (int nt = 0; nt < 4; nt++) {
            int cidx = col0 + wn + nt * 8 + t4 * 2;
            if (cidx < N) {
                *(float2*)&C[(size_t)r * N + cidx] = make_float2(acc[mt][nt][0], acc[mt][nt][1]);
                *(float2*)&C[(size_t)(r + 8) * N + cidx] = make_float2(acc[mt][nt][2], acc[mt][nt][3]);
            }
        }
    }
}

// ---------------- depthwise causal conv (K=4) + bias + SiLU ----------------
__global__ void conv_silu_kernel(const float* __restrict__ conv_w,
                                 const float* __restrict__ conv_b)
{
    size_t idx = (size_t)blockIdx.x * blockDim.x + threadIdx.x;
    const size_t total = (size_t)BB * LL * CONV;
    if (idx >= total) return;
    int ch = (int)(idx % CONV);
    size_t bl = idx / CONV;
    int l = (int)(bl % LL);

    float acc = conv_b[ch];
#pragma unroll
    for (int k = 0; k < KK; k++) {
        int ls = l - (KK - 1) + k;
        if (ls >= 0)
            acc += g_proj[(bl - (KK - 1) + k) * PROJ + DI + ch] * conv_w[ch * KK + k];
    }
    g_hbc[idx] = acc / (1.f + __expf(-acc));
}

// ---------------- dt = softplus(raw + bias); cum = chunk-cumsum(dt*A) ------
__global__ void dtcum_kernel(const float* __restrict__ dt_bias,
                             const float* __restrict__ A_log)
{
    int gw   = (blockIdx.x * blockDim.x + threadIdx.x) >> 5;
    int lane = threadIdx.x & 31;
    if (gw >= BB * CC * HH) return;
    int h  = gw % HH;
    int bc = gw / HH;
    int c  = bc % CC;
    int b  = bc / CC;

    float bias = dt_bias[h];
    float Ah   = -__expf(A_log[h]);
    float carry = 0.f;

    for (int t = 0; t < CHUNK / 32; t++) {
        int l = c * CHUNK + t * 32 + lane;
        size_t row = (size_t)b * LL + l;
        float v = g_proj[row * PROJ + DI + CONV + h] + bias;
        float dtv = (v > 20.f) ? v : log1pf(__expf(v));
        g_dt[row * HH + h] = dtv;
        float s = dtv * Ah;
#pragma unroll
        for (int off = 1; off < 32; off <<= 1) {
            float y = __shfl_up_sync(0xffffffffu, s, off);
            if (lane >= off) s += y;
        }
        float cum = carry + s;
        g_cum[row * HH + h] = cum;
        carry = __shfl_sync(0xffffffffu, cum, 31);
    }
}

// ---------------- head-independent scores: s[i,j] = C_i . B_j --------------
__global__ void scores_kernel()
{
    if (blockIdx.y < blockIdx.x) return;
    int bc = blockIdx.z;
    int b = bc / CC, c = bc % CC;
    int i0 = blockIdx.y * 32, j0 = blockIdx.x * 32;

    __shared__ float Cs[32][129];
    __shared__ float Bsh[32][129];

    int tx = threadIdx.x, ty = threadIdx.y;
    size_t baseRow = (size_t)b * LL + c * CHUNK;

#pragma unroll
    for (int q = 0; q < 4; q++) {
        int n = tx + 32 * q;
        Cs[ty][n]  = g_hbc[(baseRow + i0 + ty) * CONV + DI + NST + n];
        Bsh[ty][n] = g_hbc[(baseRow + j0 + ty) * CONV + DI + n];
    }
    __syncthreads();

    float acc = 0.f;
#pragma unroll
    for (int n = 0; n < NST; n++) acc += Cs[ty][n] * Bsh[tx][n];

    g_s[(size_t)bc * CHUNK * CHUNK + (size_t)(i0 + ty) * CHUNK + j0 + tx] = acc;
}

// ---------------- per-chunk states ------------------------------------------
__global__ __launch_bounds__(256) void states_kernel()
{
    int bch = blockIdx.x;
    int h  = bch % HH;
    int bc = bch / HH;
    int c  = bc % CC, b = bc / CC;

    __shared__ float xs[32][64];
    __shared__ float Bsh[32][129];
    __shared__ float wsh[32];

    int tid = threadIdx.x;
    int p  = tid & 63;
    int n0 = (tid >> 6) * 32;
    size_t baseRow = (size_t)b * LL + c * CHUNK;
    float cumlast = g_cum[(baseRow + CHUNK - 1) * HH + h];

    float acc[32];
#pragma unroll
    for (int k = 0; k < 32; k++) acc[k] = 0.f;

    for (int lt = 0; lt < CHUNK; lt += 32) {
        for (int q = tid; q < 32 * 64; q += 256) {
            int ll = q >> 6, pp = q & 63;
            xs[ll][pp] = g_hbc[(baseRow + lt + ll) * CONV + h * PP + pp];
        }
        for (int q = tid; q < 32 * 128; q += 256) {
            int ll = q >> 7, nn = q & 127;
            Bsh[ll][nn] = g_hbc[(baseRow + lt + ll) * CONV + DI + nn];
        }
        if (tid < 32) {
            size_t r = baseRow + lt + tid;
            wsh[tid] = __expf(cumlast - g_cum[r * HH + h]) * g_dt[r * HH + h];
        }
        __syncthreads();
#pragma unroll 4
        for (int ll = 0; ll < 32; ll++) {
            float xv = wsh[ll] * xs[ll][p];
#pragma unroll
            for (int k = 0; k < 32; k++) acc[k] += xv * Bsh[ll][n0 + k];
        }
        __syncthreads();
    }

    size_t ob = ((size_t)bch * PP + p) * NST + n0;
#pragma unroll
    for (int k = 0; k < 32; k++) g_states[ob + k] = acc[k];
}

// ---------------- inter-chunk scan ------------------------------------------
__global__ void scan_kernel()
{
    int idx = blockIdx.x * blockDim.x + threadIdx.x;
    if (idx >= BB * HH * PP * NST) return;
    int n = idx & 127;
    int p = (idx >> 7) & 63;
    int h = (idx >> 13) & 63;
    int b = idx >> 19;

    float prev = 0.f;
#pragma unroll
    for (int c = 0; c < CC; c++) {
        size_t sidx = ((((size_t)(b * CC + c) * HH + h) * PP + p) * NST) + n;
        g_prev[sidx] = prev;
        float cd = __expf(g_cum[((size_t)b * LL + c * CHUNK + CHUNK - 1) * HH + h]);
        prev = cd * prev + g_states[sidx];
    }
}

// ---------------- ycomb v2: register-blocked + factorized exp ---------------
// grid = BB*CC*HH*4 blocks; block handles one 64-row i-tile of one (b,c,h).
// thread: 2 i x 8 p.  smem: 2*64*68 floats (s+x tiles / prevT union).
__global__ __launch_bounds__(256) void ycomb_kernel(const float* __restrict__ D_param)
{
    int blk = blockIdx.x;
    int it  = blk & 3;
    int bch = blk >> 2;
    int h  = bch % HH;
    int bc = bch / HH;
    int c  = bc % CC, b = bc / CC;

    __shared__ float sm[2 * 64 * 68];     // phase A: s tile [64][68] + x tile [64][68]
                                          // phase B: prevT  [128][68]
    __shared__ float s_cumj[64], s_dtj[64], s_wj[64];
    const int XOFF = 64 * 68;

    const int tid = threadIdx.x;
    const int p0  = (tid & 7) * 8;
    const int ig  = tid >> 3;             // 0..31
    const int il0 = ig * 2, il1 = il0 + 1;

    size_t baseRow = (size_t)b * LL + c * CHUNK;
    const int gi0 = it * 64 + il0;
    const float cumi0 = g_cum[(baseRow + gi0) * HH + h];
    const float cumi1 = g_cum[(baseRow + gi0 + 1) * HH + h];

    float acc0[8], acc1[8];
#pragma unroll
    for (int q = 0; q < 8; q++) { acc0[q] = 0.f; acc1[q] = 0.f; }

    // ---------- phase A: intra-chunk (diag) term ----------
    for (int jt = 0; jt <= it; jt++) {
        // stage s tile [64 i][64 j] and x tile [64 j][64 p]
        for (int q = tid; q < 64 * 16; q += 256) {
            int r = q >> 4, c4 = (q & 15) * 4;
            float4 v = *(const float4*)&g_s[((size_t)bc * CHUNK + it * 64 + r) * CHUNK + jt * 64 + c4];
            *(float4*)&sm[r * 68 + c4] = v;
            float4 xv = *(const float4*)&g_hbc[(baseRow + jt * 64 + r) * CONV + h * PP + c4];
            *(float4*)&sm[XOFF + r * 68 + c4] = xv;
        }
        if (tid < 64) {
            size_t r = baseRow + jt * 64 + tid;
            s_cumj[tid] = g_cum[r * HH + h];
            s_dtj[tid]  = g_dt[r * HH + h];
        }
        __syncthreads();
        float cm = s_cumj[63];
        if (jt < it && tid < 64)
            s_wj[tid] = __expf(cm - s_cumj[tid]) * s_dtj[tid];
        __syncthreads();

        if (jt < it) {
            // off-diagonal: factorized exp
            float E0 = __expf(cumi0 - cm);
            float E1 = __expf(cumi1 - cm);
#pragma unroll 4
            for (int jj = 0; jj < 64; jj++) {
                float wj = s_wj[jj];
                float w0 = sm[il0 * 68 + jj] * wj * E0;
                float w1 = sm[il1 * 68 + jj] * wj * E1;
                float4 xa = *(const float4*)&sm[XOFF + jj * 68 + p0];
                float4 xb = *(const float4*)&sm[XOFF + jj * 68 + p0 + 4];
                acc0[0] += w0 * xa.x; acc0[1] += w0 * xa.y; acc0[2] += w0 * xa.z; acc0[3] += w0 * xa.w;
                acc0[4] += w0 * xb.x; acc0[5] += w0 * xb.y; acc0[6] += w0 * xb.z; acc0[7] += w0 * xb.w;
                acc1[0] += w1 * xa.x; acc1[1] += w1 * xa.y; acc1[2] += w1 * xa.z; acc1[3] += w1 * xa.w;
                acc1[4] += w1 * xb.x; acc1[5] += w1 * xb.y; acc1[6] += w1 * xb.z; acc1[7] += w1 * xb.w;
            }
        } else {
            // diagonal tile: exact exp with causal mask
            for (int jj = 0; jj < 64; jj++) {
                float cj = s_cumj[jj], dj = s_dtj[jj];
                float w0 = (jj <= il0) ? sm[il0 * 68 + jj] * __expf(cumi0 - cj) * dj : 0.f;
                float w1 = (jj <= il1) ? sm[il1 * 68 + jj] * __expf(cumi1 - cj) * dj : 0.f;
                float4 xa = *(const float4*)&sm[XOFF + jj * 68 + p0];
                float4 xb = *(const float4*)&sm[XOFF + jj * 68 + p0 + 4];
                acc0[0] += w0 * xa.x; acc0[1] += w0 * xa.y; acc0[2] += w0 * xa.z; acc0[3] += w0 * xa.w;
                acc0[4] += w0 * xb.x; acc0[5] += w0 * xb.y; acc0[6] += w0 * xb.z; acc0[7] += w0 * xb.w;
                acc1[0] += w1 * xa.x; acc1[1] += w1 * xa.y; acc1[2] += w1 * xa.z; acc1[3] += w1 * xa.w;
                acc1[4] += w1 * xb.x; acc1[5] += w1 * xb.y; acc1[6] += w1 * xb.z; acc1[7] += w1 * xb.w;
            }
        }
        __syncthreads();
    }

    // ---------- phase B: inter-chunk (off) term ----------
    {
        size_t pbase = (size_t)bch * PP * NST;
        for (int q = tid; q < 64 * 32; q += 256) {
            int p = q >> 5, n4 = (q & 31) * 4;
            float4 v = *(const float4*)&g_prev[pbase + (size_t)p * NST + n4];
            sm[(n4 + 0) * 68 + p] = v.x;
            sm[(n4 + 1) * 68 + p] = v.y;
            sm[(n4 + 2) * 68 + p] = v.z;
            sm[(n4 + 3) * 68 + p] = v.w;
        }
        __syncthreads();

        float e0 = __expf(cumi0);
        float e1 = __expf(cumi1);
        const float* C0 = &g_hbc[(baseRow + gi0) * CONV + DI + NST];
        const float* C1 = C0 + CONV;
#pragma unroll 2
        for (int n = 0; n < NST; n += 4) {
            float4 ca = *(const float4*)&C0[n];
            float4 cb = *(const float4*)&C1[n];
#pragma unroll
            for (int k = 0; k < 4; k++) {
                float cav = (k == 0) ? ca.x : (k == 1) ? ca.y : (k == 2) ? ca.z : ca.w;
                float cbv = (k == 0) ? cb.x : (k == 1) ? cb.y : (k == 2) ? cb.z : cb.w;
                float w0 = e0 * cav, w1 = e1 * cbv;
                const float* xp = &sm[(n + k) * 68 + p0];
                float4 xa = *(const float4*)xp;
                float4 xb = *(const float4*)(xp + 4);
                acc0[0] += w0 * xa.x; acc0[1] += w0 * xa.y; acc0[2] += w0 * xa.z; acc0[3] += w0 * xa.w;
                acc0[4] += w0 * xb.x; acc0[5] += w0 * xb.y; acc0[6] += w0 * xb.z; acc0[7] += w0 * xb.w;
                acc1[0] += w1 * xa.x; acc1[1] += w1 * xa.y; acc1[2] += w1 * xa.z; acc1[3] += w1 * xa.w;
                acc1[4] += w1 * xb.x; acc1[5] += w1 * xb.y; acc1[6] += w1 * xb.z; acc1[7] += w1 * xb.w;
            }
        }
    }

    // ---------- phase C: + D*x, write ----------
    {
        float Dh = D_param[h];
        const float* x0 = &g_hbc[(baseRow + gi0) * CONV + h * PP + p0];
        const float* x1 = x0 + CONV;
        float* y0 = &g_y[(baseRow + gi0) * DI + h * PP + p0];
        float* y1 = y0 + DI;
        float4 o;
        o = make_float4(acc0[0] + Dh * x0[0], acc0[1] + Dh * x0[1], acc0[2] + Dh * x0[2], acc0[3] + Dh * x0[3]);
        *(float4*)y0 = o;
        o = make_float4(acc0[4] + Dh * x0[4], acc0[5] + Dh * x0[5], acc0[6] + Dh * x0[6], acc0[7] + Dh * x0[7]);
        *(float4*)(y0 + 4) = o;
        o = make_float4(acc1[0] + Dh * x1[0], acc1[1] + Dh * x1[1], acc1[2] + Dh * x1[2], acc1[3] + Dh * x1[3]);
        *(float4*)y1 = o;
        o = make_float4(acc1[4] + Dh * x1[4], acc1[5] + Dh * x1[5], acc1[6] + Dh * x1[6], acc1[7] + Dh * x1[7]);
        *(float4*)(y1 + 4) = o;
    }
}

// ---------------- gated RMSNorm ----------------------------------------------
__global__ __launch_bounds__(256) void gatenorm_kernel(const float* __restrict__ norm_w)
{
    int row = blockIdx.x;
    __shared__ float sh[DI];
    __shared__ float red[256];

    const float* yrow = &g_y[(size_t)row * DI];
    const float* grow = &g_proj[(size_t)row * PROJ];

    float local = 0.f;
    for (int d = threadIdx.x; d < DI; d += 256) {
        float g  = grow[d];
        float hv = yrow[d] * (g / (1.f + __expf(-g)));
        sh[d] = hv;
        local += hv * hv;
    }
    red[threadIdx.x] = local;
    __syncthreads();
    for (int s = 128; s > 0; s >>= 1) {
        if (threadIdx.x < s) red[threadIdx.x] += red[threadIdx.x + s];
        __syncthreads();
    }
    float rms = rsqrtf(red[0] / (float)DI + EPSV);

    float* orow = &g_y[(size_t)row * DI];
    for (int d = threadIdx.x; d < DI; d += 256)
        orow[d] = sh[d] * rms * norm_w[d];
}

// ---------------- launcher ---------------------------------------------------
extern "C" void kernel_launch(void* const* d_in, const int* in_sizes, int n_in,
                              void* d_out, int out_size)
{
    const float* hs       = (const float*)d_in[0];
    const float* in_proj  = (const float*)d_in[1];
    const float* conv_w   = (const float*)d_in[2];
    const float* conv_b   = (const float*)d_in[3];
    const float* dt_bias  = (const float*)d_in[4];
    const float* A_log    = (const float*)d_in[5];
    const float* D_param  = (const float*)d_in[6];
    const float* norm_w   = (const float*)d_in[7];
    const float* out_proj = (const float*)d_in[8];
    float* out = (float*)d_out;

    float* proj_ptr;   cudaGetSymbolAddress((void**)&proj_ptr, g_proj);
    float* y_ptr;      cudaGetSymbolAddress((void**)&y_ptr, g_y);

    const int M = BB * LL;   // 4096

    // 1) in-projection GEMM (tf32 tensor cores, double-buffered)
    {
        dim3 grid((PROJ + 127) / 128, M / 128);
        tf32_gemm_kernel<<<grid, 256>>>(hs, in_proj, proj_ptr, M, PROJ, DM);
    }
    // 2) depthwise conv + silu
    {
        size_t total = (size_t)BB * LL * CONV;
        conv_silu_kernel<<<(unsigned)((total + 255) / 256), 256>>>(conv_w, conv_b);
    }
    // 3) dt softplus + chunk cumsum
    dtcum_kernel<<<(BB * CC * HH * 32 + 255) / 256, 256>>>(dt_bias, A_log);
    // 4) head-independent CB scores
    {
        dim3 grid(CHUNK / 32, CHUNK / 32, BB * CC);
        scores_kernel<<<grid, dim3(32, 32)>>>();
    }
    // 5) per-chunk states
    states_kernel<<<BB * CC * HH, 256>>>();
    // 6) inter-chunk scan
    scan_kernel<<<(BB * HH * PP * NST + 255) / 256, 256>>>();
    // 7) Y = diag + off + D*x   (64-row i-tiles)
    ycomb_kernel<<<BB * CC * HH * 4, 256>>>(D_param);
    // 8) gated RMSNorm
    gatenorm_kernel<<<BB * LL, 256>>>(norm_w);
    // 9) out-projection GEMM (tf32)
    {
        dim3 grid(DM / 128, M / 128);
        tf32_gemm_kernel<<<grid, 256>>>(y_ptr, out_proj, out, M, DM, DI);
    }
    (void)in_sizes; (void)n_in; (void)out_size;
}